// round 3
// baseline (speedup 1.0000x reference)
#include <cuda_runtime.h>

// MHSA_fl_bs — analytic collapse.
//
// The reference applies softmax over the HEAD axis of scores broadcast
// identically across all H=16 heads => attn == 1/16 exactly, everywhere,
// independent of the scores. Hence q, k, Wq, bq, Wk, bk are dead and:
//   vsum[b,d]  = sum_q v[b,q,d]
//   s[b,d']    = dot(vsum[b,:], Wv[d',:]) + Sq*bv[d']
//   o[b,d]     = bb[d] + (1/16) * dot(s[b,:], Wb[d,:])
//   out[k,b,d] = o[b,d]   (broadcast over all Sk positions)
//
// Shapes: B=4, Sq=Sk=1024, D=1024, dh=64, H=16.
// Cost is purely memory: 16 MB read (v) + 16 MB write (out). 3 launches.

#define BB     4
#define SQ     1024
#define SK     1024
#define DD     1024
#define DH     64
#define HINV   (1.0f / 16.0f)
#define QCHUNK 16
#define NCHUNK (SQ / QCHUNK)     // 64 partial rows per batch

__device__ float g_part[BB * NCHUNK * DD];   // per-chunk partial sums (1 MB)
__device__ float g_o[BB * DD];               // final per-batch output row

// ---------------------------------------------------------------------------
// Stage 1: grid (BB, NCHUNK) = 256 blocks, 256 threads. Each block reduces
// QCHUNK=16 q-rows of one batch (float4-wide) and stores the partial row.
// Pure coalesced 16 MB read stream + 1 MB write. No atomics, no zero-init.
__global__ void k_vsum(const float4* __restrict__ v) {
    const int b  = blockIdx.x;
    const int qc = blockIdx.y;
    const int d4 = threadIdx.x;                 // 0..255

    const float4* base = v + ((size_t)b * SQ + (size_t)qc * QCHUNK) * (DD / 4) + d4;
    float4 acc = make_float4(0.f, 0.f, 0.f, 0.f);
#pragma unroll
    for (int q = 0; q < QCHUNK; ++q) {
        float4 x = base[(size_t)q * (DD / 4)];
        acc.x += x.x; acc.y += x.y; acc.z += x.z; acc.w += x.w;
    }
    ((float4*)g_part)[((size_t)b * NCHUNK + qc) * (DD / 4) + d4] = acc;
}

// ---------------------------------------------------------------------------
// Stage 2: grid BB, block 1024. Fused: reduce partials -> vsum (shared),
// compute s[64] (16 lanes per output, shuffle-reduced), compute o[b,:].
__global__ void k_mid(const float* __restrict__ Wv, const float* __restrict__ bv,
                      const float* __restrict__ Wb, const float* __restrict__ bb_) {
    __shared__ float vsum[DD];
    __shared__ float s[DH];

    const int b   = blockIdx.x;
    const int tid = threadIdx.x;

    // --- reduce 64 partial rows into vsum (coalesced: stride DD across qc) ---
    {
        const float* p = g_part + (size_t)b * NCHUNK * DD + tid;
        float acc = 0.0f;
#pragma unroll 8
        for (int qc = 0; qc < NCHUNK; ++qc)
            acc += p[(size_t)qc * DD];
        vsum[tid] = acc;
    }
    __syncthreads();

    // --- s[dp] = dot(vsum, Wv[dp,:]) + Sq*bv[dp]; 16 lanes per dp ---
    {
        const int dp   = tid >> 4;      // 0..63
        const int lane = tid & 15;      // 0..15
        const float4* wrow = (const float4*)(Wv + (size_t)dp * DD);
        float acc = 0.0f;
#pragma unroll
        for (int j = 0; j < (DD / 4) / 16; ++j) {   // 16 float4s per lane
            float4 w = wrow[lane + j * 16];
            const float* x = &vsum[(lane + j * 16) * 4];
            acc += w.x * x[0] + w.y * x[1] + w.z * x[2] + w.w * x[3];
        }
        // reduce across the 16 lanes of this half-warp
#pragma unroll
        for (int off = 8; off > 0; off >>= 1)
            acc += __shfl_down_sync(0xFFFFFFFFu, acc, off, 16);
        if (lane == 0) s[dp] = acc + (float)SQ * bv[dp];
    }
    __syncthreads();

    // --- o[b,d] = bb[d] + (1/16) * dot(s, Wb[d,:]) ---
    {
        const int d = tid;
        const float4* wrow = (const float4*)(Wb + (size_t)d * DH);
        float acc = 0.0f;
#pragma unroll
        for (int i = 0; i < DH / 4; ++i) {
            float4 w = wrow[i];
            acc += w.x * s[4 * i] + w.y * s[4 * i + 1] +
                   w.z * s[4 * i + 2] + w.w * s[4 * i + 3];
        }
        g_o[b * DD + d] = acc * HINV + bb_[d];
    }
}

// ---------------------------------------------------------------------------
// Stage 3: broadcast o[b,:] across all Sk. out layout [Sk, B, D]. Each
// thread writes KREP float4s (consecutive k, same (b,d4)) from one
// register-held value. Pure coalesced 16 MB write; g_o stays L2-resident.
#define KREP 4
__global__ void k_bcast(float4* __restrict__ out) {
    const int i   = blockIdx.x * blockDim.x + threadIdx.x;
    const int row = i >> 8;        // (k_base, b) row; 256 float4 per row
    const int d4  = i & 255;
    const int b   = row & 3;
    const int k0  = (row >> 2) * KREP;

    const float4 val = ((const float4*)g_o)[b * 256 + d4];
    float4* dst = out + (((size_t)k0 * BB + b) << 8) + d4;
#pragma unroll
    for (int r = 0; r < KREP; ++r)
        dst[(size_t)r * BB * (DD / 4)] = val;
}

// ---------------------------------------------------------------------------
extern "C" void kernel_launch(void* const* d_in, const int* in_sizes, int n_in,
                              void* d_out, int out_size) {
    // metadata order: q, k, h, w, v, Wq, bq, Wk, bk, Wv, bv, Wb, bb
    const float* v  = (const float*)d_in[4];
    const float* Wv = (const float*)d_in[9];
    const float* bv = (const float*)d_in[10];
    const float* Wb = (const float*)d_in[11];
    const float* bb = (const float*)d_in[12];

    dim3 g1(BB, NCHUNK);
    k_vsum<<<g1, 256>>>((const float4*)v);

    k_mid<<<BB, DD>>>(Wv, bv, Wb, bb);

    k_bcast<<<(SK / KREP) * BB * (DD / 4) / 256, 256>>>((float4*)d_out);
}